// round 3
// baseline (speedup 1.0000x reference)
#include <cuda_runtime.h>
#include <math.h>

#define NB 2
#define LL 1024
#define SS 1024
#define HH 8
#define EE 64
#define KK 6

// Scratch (static device globals: allocation-free rule)
__device__ float g_ht[(size_t)KK*NB*HH*LL*EE];   // htilde[c][n][h][l][e]  (~25 MB)
__device__ float g_hsq[(size_t)KK*NB*HH*LL];     // ||htilde||^2
__device__ float g_pi[(size_t)NB*HH*LL*KK];      // mixture weights [n][h][l][c]
__device__ float g_keyT[(size_t)NB*HH*EE*SS];    // key transposed [n][h][e][s]
__device__ float g_ksq[(size_t)NB*HH*SS];        // ||key||^2 [n][h][s]

// ---------------------------------------------------------------------------
// Kernel 1: pi = softmax_k(q.M), htilde[c] = tanh(q.C[c]), hsq
// grid (16 l-tiles, H, N), 256 threads; each block owns 64 l-rows of one (n,h)
// ---------------------------------------------------------------------------
__global__ __launch_bounds__(256) void precompute_kernel(
    const float* __restrict__ q, const float* __restrict__ M,
    const float* __restrict__ C)
{
  int lt = blockIdx.x, h = blockIdx.y, n = blockIdx.z;
  int l0 = lt * 64;
  int tid = threadIdx.x;
  __shared__ float sq[64][65];   // q tile, padded (stride-64 row reads)
  __shared__ float sc[64][64];   // C[c][h] tile
  __shared__ float sz[64][KK];
  __shared__ float spart[64][4];

  for (int idx = tid; idx < 4096; idx += 256) {
    int l = idx >> 6, e = idx & 63;
    sq[l][e] = q[((size_t)((n*LL + l0 + l)*HH + h))*EE + e];
  }
  __syncthreads();

  // pi logits + softmax over K=6
  for (int t = tid; t < 64*KK; t += 256) {
    int l = t / KK, k = t % KK;
    float a = 0.f;
    for (int e = 0; e < EE; e++) a += sq[l][e] * M[(h*EE + e)*KK + k];
    sz[l][k] = a;
  }
  __syncthreads();
  if (tid < 64) {
    float mx = sz[tid][0];
    #pragma unroll
    for (int k = 1; k < KK; k++) mx = fmaxf(mx, sz[tid][k]);
    float s = 0.f, ev[KK];
    #pragma unroll
    for (int k = 0; k < KK; k++) { ev[k] = __expf(sz[tid][k] - mx); s += ev[k]; }
    float inv = 1.f / s;
    #pragma unroll
    for (int k = 0; k < KK; k++)
      g_pi[((size_t)((n*HH + h)*LL) + l0 + tid)*KK + k] = ev[k]*inv;
  }

  int lq = tid >> 2;       // row 0..63
  int f0 = tid & 3;        // this thread owns f = f0 + 4j
  for (int c = 0; c < KK; c++) {
    __syncthreads();
    for (int idx = tid; idx < 4096; idx += 256)
      sc[idx >> 6][idx & 63] = C[(size_t)(c*HH + h)*4096 + idx];
    __syncthreads();

    float a[16];
    #pragma unroll
    for (int j = 0; j < 16; j++) a[j] = 0.f;
    for (int e = 0; e < EE; e++) {
      float qv = sq[lq][e];
      #pragma unroll
      for (int j = 0; j < 16; j++) a[j] += qv * sc[e][f0 + 4*j];
    }
    float ssq = 0.f;
    size_t htbase = ((size_t)((c*NB + n)*HH + h)*LL + l0 + lq)*EE;
    #pragma unroll
    for (int j = 0; j < 16; j++) {
      float t = tanhf(a[j]);
      ssq += t*t;
      g_ht[htbase + f0 + 4*j] = t;
    }
    spart[lq][f0] = ssq;
    __syncthreads();
    if (tid < 64)
      g_hsq[(size_t)((c*NB + n)*HH + h)*LL + l0 + tid] =
        spart[tid][0] + spart[tid][1] + spart[tid][2] + spart[tid][3];
  }
}

// ---------------------------------------------------------------------------
// Kernel 2: key transpose -> g_keyT[n][h][e][s], and ksq
// ---------------------------------------------------------------------------
__global__ __launch_bounds__(256) void keyprep_kernel(const float* __restrict__ key)
{
  int st = blockIdx.x, h = blockIdx.y, n = blockIdx.z;
  int s0 = st * 64;
  int tid = threadIdx.x;
  __shared__ float sk[64][65];
  for (int idx = tid; idx < 4096; idx += 256) {
    int s = idx >> 6, e = idx & 63;
    sk[s][e] = key[((size_t)((n*SS + s0 + s)*HH + h))*EE + e];
  }
  __syncthreads();
  for (int idx = tid; idx < 4096; idx += 256) {
    int e = idx >> 6, s = idx & 63;
    g_keyT[((size_t)((n*HH + h)*EE) + e)*SS + s0 + s] = sk[s][e];
  }
  if (tid < 64) {
    float a = 0.f;
    #pragma unroll
    for (int e = 0; e < EE; e++) a += sk[tid][e] * sk[tid][e];
    g_ksq[(size_t)(n*HH + h)*SS + s0 + tid] = a;
  }
}

// ---------------------------------------------------------------------------
// Kernel 3: fused 6-code logits + softmax + mixture accumulation
// grid (L/16, H, N), 512 threads. Thread tile: 4 l-rows x 8 s (stride-128 s).
// ---------------------------------------------------------------------------
#define TLm 16
#define ECm 8

__device__ __forceinline__ float kfun(int c, float d, float ns) {
  if (c == 0) return d;                                   // 'L'
  if (c == 1) return -log1pf(ns);                         // 'O'
  if (c == 2) return -ns;                                 // 'P'
  if (c == 3) { float t = d + 1.f; return t * t; }        // 'Y'
  if (c == 4) return __expf(-0.5f * ns);                  // 'R'
  return __cosf(ns) * __expf(-ns);                        // 'W'
}

__global__ __launch_bounds__(512) void attn_kernel(
    const float* __restrict__ mask, const float* __restrict__ keylen,
    float* __restrict__ out)
{
  int lt = blockIdx.x, h = blockIdx.y, n = blockIdx.z;
  int l0 = lt * TLm;
  int tid  = threadIdx.x;
  int lg   = tid >> 7;        // 0..3  -> rows lg*4 .. lg*4+3
  int si   = tid & 127;       // s = si + 128*j
  int lane = tid & 31;
  int w4   = si >> 5;         // warp within row-group

  __shared__ float s_key[ECm][SS];      // 32 KB
  __shared__ float s_ht[TLm][EE];       // 4 KB
  __shared__ float s_ksq[SS];           // 4 KB
  __shared__ float s_hsq[TLm];
  __shared__ float s_pi[TLm];
  __shared__ float s_redm[TLm][4];
  __shared__ float s_redz[TLm][4];

  for (int s = tid; s < SS; s += 512)
    s_ksq[s] = g_ksq[(size_t)(n*HH + h)*SS + s];

  float outacc[4][8];
  #pragma unroll
  for (int i = 0; i < 4; i++)
    #pragma unroll
    for (int j = 0; j < 8; j++) outacc[i][j] = 0.f;

  const float* mbase  = mask + ((size_t)n*LL + l0)*SS;
  const float* klbase = keylen + (size_t)n*SS;

  #pragma unroll
  for (int c = 0; c < 6; c++) {
    __syncthreads();
    for (int idx = tid; idx < TLm*EE; idx += 512)
      (&s_ht[0][0])[idx] =
          g_ht[((size_t)((c*NB + n)*HH + h)*LL + l0)*EE + idx];
    if (tid < TLm) {
      s_hsq[tid] = g_hsq[(size_t)((c*NB + n)*HH + h)*LL + l0 + tid];
      s_pi[tid]  = g_pi[((size_t)((n*HH + h)*LL) + l0 + tid)*KK + c];
    }

    float acc[4][8];
    #pragma unroll
    for (int i = 0; i < 4; i++)
      #pragma unroll
      for (int j = 0; j < 8; j++) acc[i][j] = 0.f;

    const float4* ksrc =
        (const float4*)(g_keyT + (size_t)((n*HH + h)*EE)*SS);
    for (int ec = 0; ec < EE/ECm; ec++) {
      __syncthreads();
      float4* kdst = (float4*)&s_key[0][0];
      #pragma unroll
      for (int t = 0; t < (ECm*SS/4)/512; t++)
        kdst[tid + t*512] = ksrc[(size_t)ec*(ECm*SS/4) + tid + t*512];
      __syncthreads();
      #pragma unroll
      for (int e = 0; e < ECm; e++) {
        float hv[4];
        #pragma unroll
        for (int i = 0; i < 4; i++) hv[i] = s_ht[lg*4 + i][ec*ECm + e];
        float kv[8];
        #pragma unroll
        for (int j = 0; j < 8; j++) kv[j] = s_key[e][si + 128*j];
        #pragma unroll
        for (int i = 0; i < 4; i++)
          #pragma unroll
          for (int j = 0; j < 8; j++) acc[i][j] += hv[i]*kv[j];
      }
    }

    // --- epilogue: transform + masked softmax + weighted accumulate ---
    float kladd[8];
    #pragma unroll
    for (int j = 0; j < 8; j++) kladd[j] = klbase[si + 128*j];
    float hsqv[4];
    #pragma unroll
    for (int i = 0; i < 4; i++) hsqv[i] = s_hsq[lg*4 + i];

    #pragma unroll
    for (int i = 0; i < 4; i++) {
      int l = lg*4 + i;
      float mm = -3.4e38f;
      #pragma unroll
      for (int j = 0; j < 8; j++) {
        int s = si + 128*j;
        float d  = acc[i][j];
        float ns = hsqv[i] + s_ksq[s] - 2.f*d;
        float f  = kfun(c, d, ns);
        f += mbase[(size_t)l*SS + s] + kladd[j];
        acc[i][j] = f;
        mm = fmaxf(mm, f);
      }
      #pragma unroll
      for (int o = 16; o; o >>= 1)
        mm = fmaxf(mm, __shfl_xor_sync(0xffffffffu, mm, o));
      if (lane == 0) s_redm[l][w4] = mm;
    }
    __syncthreads();
    float m[4];
    #pragma unroll
    for (int i = 0; i < 4; i++) {
      int l = lg*4 + i;
      m[i] = fmaxf(fmaxf(s_redm[l][0], s_redm[l][1]),
                   fmaxf(s_redm[l][2], s_redm[l][3]));
    }
    #pragma unroll
    for (int i = 0; i < 4; i++) {
      int l = lg*4 + i;
      float z = 0.f;
      #pragma unroll
      for (int j = 0; j < 8; j++) {
        float ev = __expf(acc[i][j] - m[i]);
        acc[i][j] = ev;
        z += ev;
      }
      #pragma unroll
      for (int o = 16; o; o >>= 1) z += __shfl_xor_sync(0xffffffffu, z, o);
      if (lane == 0) s_redz[l][w4] = z;
    }
    __syncthreads();
    #pragma unroll
    for (int i = 0; i < 4; i++) {
      int l = lg*4 + i;
      float Z = s_redz[l][0] + s_redz[l][1] + s_redz[l][2] + s_redz[l][3];
      float coef = s_pi[l] / Z;
      #pragma unroll
      for (int j = 0; j < 8; j++) outacc[i][j] += coef * acc[i][j];
    }
  }

  size_t obase = (size_t)((n*HH + h)*LL + l0 + lg*4)*SS + si;
  #pragma unroll
  for (int i = 0; i < 4; i++)
    #pragma unroll
    for (int j = 0; j < 8; j++)
      out[obase + (size_t)i*SS + 128*j] = outacc[i][j];
}

// ---------------------------------------------------------------------------
extern "C" void kernel_launch(void* const* d_in, const int* in_sizes, int n_in,
                              void* d_out, int out_size)
{
  const float* q    = (const float*)d_in[0];  // [2,1024,8,64]
  const float* key  = (const float*)d_in[1];  // [2,1024,8,64]
  const float* mask = (const float*)d_in[2];  // [2,1024,1024]
  const float* klen = (const float*)d_in[3];  // [2,1024]
  const float* M    = (const float*)d_in[4];  // [8,64,6]
  const float* C    = (const float*)d_in[5];  // [6,8,64,64]
  float* out = (float*)d_out;                 // [2,8,1024,1024]
  (void)in_sizes; (void)n_in; (void)out_size;

  dim3 gpre(LL/64, HH, NB), bpre(256);
  precompute_kernel<<<gpre, bpre>>>(q, M, C);
  keyprep_kernel<<<gpre, bpre>>>(key);
  dim3 gmain(LL/TLm, HH, NB), bmain(512);
  attn_kernel<<<gmain, bmain>>>(mask, klen, out);
}

// round 4
// speedup vs baseline: 1.1300x; 1.1300x over previous
#include <cuda_runtime.h>
#include <math.h>

#define NB 2
#define LL 1024
#define SS 1024
#define HH 8
#define EE 64
#define KK 6

// Scratch (static device globals: allocation-free rule)
__device__ float g_ht[(size_t)KK*NB*HH*LL*EE];   // htilde[c][n][h][l][e]
__device__ float g_hsq[(size_t)KK*NB*HH*LL];     // ||htilde||^2
__device__ float g_pi[(size_t)NB*HH*LL*KK];      // mixture weights [n][h][l][c]
__device__ float g_keyT[(size_t)NB*HH*EE*SS];    // key transposed [n][h][e][s]
__device__ float g_ksq[(size_t)NB*HH*SS];        // ||key||^2 [n][h][s]

// ---------------------------------------------------------------------------
// Kernel 1: pi = softmax_k(q.M), htilde[c] = tanh(q.C[c]), hsq
// grid (16 l-tiles, H, N*K): one code per block (6x parallelism vs R1)
// ---------------------------------------------------------------------------
__global__ __launch_bounds__(256) void precompute_kernel(
    const float* __restrict__ q, const float* __restrict__ M,
    const float* __restrict__ C)
{
  int lt = blockIdx.x, h = blockIdx.y;
  int c  = blockIdx.z >> 1;      // z = c*NB + n
  int n  = blockIdx.z & 1;
  int l0 = lt * 64;
  int tid = threadIdx.x;
  __shared__ float sq[64][65];
  __shared__ float sc[64][64];
  __shared__ float sz[64][KK];
  __shared__ float spart[64][4];

  for (int idx = tid; idx < 4096; idx += 256) {
    int l = idx >> 6, e = idx & 63;
    sq[l][e] = q[((size_t)((n*LL + l0 + l)*HH + h))*EE + e];
  }
  for (int idx = tid; idx < 4096; idx += 256)
    sc[idx >> 6][idx & 63] = C[(size_t)(c*HH + h)*4096 + idx];
  __syncthreads();

  if (c == 0) {  // pi computed once (by the c==0 blocks)
    for (int t = tid; t < 64*KK; t += 256) {
      int l = t / KK, k = t % KK;
      float a = 0.f;
      for (int e = 0; e < EE; e++) a += sq[l][e] * M[(h*EE + e)*KK + k];
      sz[l][k] = a;
    }
    __syncthreads();
    if (tid < 64) {
      float mx = sz[tid][0];
      #pragma unroll
      for (int k = 1; k < KK; k++) mx = fmaxf(mx, sz[tid][k]);
      float s = 0.f, ev[KK];
      #pragma unroll
      for (int k = 0; k < KK; k++) { ev[k] = __expf(sz[tid][k] - mx); s += ev[k]; }
      float inv = 1.f / s;
      #pragma unroll
      for (int k = 0; k < KK; k++)
        g_pi[((size_t)((n*HH + h)*LL) + l0 + tid)*KK + k] = ev[k]*inv;
    }
  }

  int lq = tid >> 2;
  int f0 = tid & 3;
  float a[16];
  #pragma unroll
  for (int j = 0; j < 16; j++) a[j] = 0.f;
  for (int e = 0; e < EE; e++) {
    float qv = sq[lq][e];
    #pragma unroll
    for (int j = 0; j < 16; j++) a[j] += qv * sc[e][f0 + 4*j];
  }
  float ssq = 0.f;
  size_t htbase = ((size_t)((c*NB + n)*HH + h)*LL + l0 + lq)*EE;
  #pragma unroll
  for (int j = 0; j < 16; j++) {
    float t = tanhf(a[j]);
    ssq += t*t;
    g_ht[htbase + f0 + 4*j] = t;
  }
  spart[lq][f0] = ssq;
  __syncthreads();
  if (tid < 64)
    g_hsq[(size_t)((c*NB + n)*HH + h)*LL + l0 + tid] =
      spart[tid][0] + spart[tid][1] + spart[tid][2] + spart[tid][3];
}

// ---------------------------------------------------------------------------
// Kernel 2: key transpose -> g_keyT[n][h][e][s], and ksq
// ---------------------------------------------------------------------------
__global__ __launch_bounds__(256) void keyprep_kernel(const float* __restrict__ key)
{
  int st = blockIdx.x, h = blockIdx.y, n = blockIdx.z;
  int s0 = st * 64;
  int tid = threadIdx.x;
  __shared__ float sk[64][65];
  for (int idx = tid; idx < 4096; idx += 256) {
    int s = idx >> 6, e = idx & 63;
    sk[s][e] = key[((size_t)((n*SS + s0 + s)*HH + h))*EE + e];
  }
  __syncthreads();
  for (int idx = tid; idx < 4096; idx += 256) {
    int e = idx >> 6, s = idx & 63;
    g_keyT[((size_t)((n*HH + h)*EE) + e)*SS + s0 + s] = sk[s][e];
  }
  if (tid < 64) {
    float a = 0.f;
    #pragma unroll
    for (int e = 0; e < EE; e++) a += sk[tid][e] * sk[tid][e];
    g_ksq[(size_t)(n*HH + h)*SS + s0 + tid] = a;
  }
}

// ---------------------------------------------------------------------------
// Kernel 3: fused logits + softmax + mixture, codes processed in PAIRS
// grid (L/16, H, N), 512 threads. Thread tile: 4 l x 8 s (stride-128) x 2 codes.
// Dynamic smem: 2x32KB key (double buffer) + 64KB out acc + ht/ksq/etc.
// ---------------------------------------------------------------------------
#define TLm 16
#define ECm 8

// smem float offsets
#define SMO_KEY   0          // 2 * 8192
#define SMO_OUT   16384      // 16384
#define SMO_HT    32768      // 2048
#define SMO_KSQ   34816      // 1024
#define SMO_HSQ   35840      // 32
#define SMO_PI    35872      // 32
#define SMO_REDM  35904      // 64
#define SMO_REDZ  35968      // 64
#define SMEM_FLOATS 36032
#define SMEM_BYTES (SMEM_FLOATS*4)

__device__ __forceinline__ float kfun(int c, float d, float ns) {
  if (c == 0) return d;                                   // 'L'
  if (c == 1) return -log1pf(ns);                         // 'O'
  if (c == 2) return -ns;                                 // 'P'
  if (c == 3) { float t = d + 1.f; return t * t; }        // 'Y'
  if (c == 4) return __expf(-0.5f * ns);                  // 'R'
  return __cosf(ns) * __expf(-ns);                        // 'W'
}

__global__ __launch_bounds__(512) void attn_kernel(
    const float* __restrict__ mask, const float* __restrict__ keylen,
    float* __restrict__ out)
{
  extern __shared__ float sm[];
  float* s_key  = sm + SMO_KEY;
  float* s_out  = sm + SMO_OUT;
  float* s_ht2  = sm + SMO_HT;
  float* s_ksq  = sm + SMO_KSQ;
  float* s_hsq2 = sm + SMO_HSQ;
  float* s_pi2  = sm + SMO_PI;
  float* s_redm = sm + SMO_REDM;
  float* s_redz = sm + SMO_REDZ;

  int lt = blockIdx.x, h = blockIdx.y, n = blockIdx.z;
  int l0 = lt * TLm;
  int tid  = threadIdx.x;
  int lg   = tid >> 7;        // 0..3  -> rows lg*4 .. lg*4+3
  int si   = tid & 127;       // s = si + 128*j
  int lane = tid & 31;
  int w4   = si >> 5;

  for (int idx = tid; idx < TLm*SS; idx += 512) s_out[idx] = 0.f;
  for (int s = tid; s < SS; s += 512)
    s_ksq[s] = g_ksq[(size_t)(n*HH + h)*SS + s];

  const float*  mbase  = mask + ((size_t)n*LL + l0)*SS;
  const float*  klbase = keylen + (size_t)n*SS;
  const float4* ksrc   = (const float4*)(g_keyT + (size_t)((n*HH + h)*EE)*SS);

  #pragma unroll
  for (int p = 0; p < 3; p++) {
    const int c0 = 2*p;
    __syncthreads();   // prev epilogue reads done before rewriting below

    for (int idx = tid; idx < 2*TLm*EE; idx += 512) {
      int cc = idx >> 10, off = idx & 1023;
      s_ht2[idx] = g_ht[((size_t)(((c0+cc)*NB + n)*HH + h)*LL + l0)*EE + off];
    }
    if (tid < 2*TLm) {
      int cc = tid >> 4, l = tid & 15;
      s_hsq2[tid] = g_hsq[(size_t)(((c0+cc)*NB + n)*HH + h)*LL + l0 + l];
      s_pi2[tid]  = g_pi[((size_t)((n*HH + h)*LL) + l0 + l)*KK + c0 + cc];
    }

    // prefetch chunk 0, stage into buffer 0 (safe: both buffers idle here)
    float4 pf[4];
    #pragma unroll
    for (int t = 0; t < 4; t++) pf[t] = ksrc[tid + t*512];
    float4* kb = (float4*)s_key;
    #pragma unroll
    for (int t = 0; t < 4; t++) kb[tid + t*512] = pf[t];
    __syncthreads();

    float acc[2][4][8];
    #pragma unroll
    for (int cc = 0; cc < 2; cc++)
      #pragma unroll
      for (int i = 0; i < 4; i++)
        #pragma unroll
        for (int j = 0; j < 8; j++) acc[cc][i][j] = 0.f;

    #pragma unroll 1
    for (int ec = 0; ec < EE/ECm; ec++) {
      if (ec + 1 < EE/ECm) {
        #pragma unroll
        for (int t = 0; t < 4; t++)
          pf[t] = ksrc[(ec+1)*(ECm*SS/4) + tid + t*512];
      }
      const float* kcur = s_key + (ec & 1) * (ECm*SS);
      #pragma unroll
      for (int e = 0; e < ECm; e++) {
        float kv[8];
        #pragma unroll
        for (int j = 0; j < 8; j++) kv[j] = kcur[e*SS + si + 128*j];
        float hv[2][4];
        #pragma unroll
        for (int cc = 0; cc < 2; cc++)
          #pragma unroll
          for (int i = 0; i < 4; i++)
            hv[cc][i] = s_ht2[cc*1024 + (lg*4 + i)*EE + ec*ECm + e];
        #pragma unroll
        for (int cc = 0; cc < 2; cc++)
          #pragma unroll
          for (int i = 0; i < 4; i++)
            #pragma unroll
            for (int j = 0; j < 8; j++)
              acc[cc][i][j] += hv[cc][i] * kv[j];
      }
      if (ec + 1 < EE/ECm) {
        float4* kdst = (float4*)(s_key + ((ec+1) & 1) * (ECm*SS));
        #pragma unroll
        for (int t = 0; t < 4; t++) kdst[tid + t*512] = pf[t];
        __syncthreads();
      }
    }

    // --- epilogue: transform + masked softmax + weighted accumulate ---
    float kladd[8];
    #pragma unroll
    for (int j = 0; j < 8; j++) kladd[j] = klbase[si + 128*j];

    #pragma unroll
    for (int cc = 0; cc < 2; cc++) {
      float hsqv[4];
      #pragma unroll
      for (int i = 0; i < 4; i++) hsqv[i] = s_hsq2[cc*16 + lg*4 + i];

      #pragma unroll
      for (int i = 0; i < 4; i++) {
        int l = lg*4 + i;
        float mm = -3.4e38f;
        #pragma unroll
        for (int j = 0; j < 8; j++) {
          int s = si + 128*j;
          float d  = acc[cc][i][j];
          float ns = hsqv[i] + s_ksq[s] - 2.f*d;
          float f  = kfun(c0 + cc, d, ns);
          f += mbase[(size_t)l*SS + s] + kladd[j];
          acc[cc][i][j] = f;
          mm = fmaxf(mm, f);
        }
        #pragma unroll
        for (int o = 16; o; o >>= 1)
          mm = fmaxf(mm, __shfl_xor_sync(0xffffffffu, mm, o));
        if (lane == 0) s_redm[l*4 + w4] = mm;
      }
      __syncthreads();
      float m[4];
      #pragma unroll
      for (int i = 0; i < 4; i++) {
        int l = lg*4 + i;
        m[i] = fmaxf(fmaxf(s_redm[l*4+0], s_redm[l*4+1]),
                     fmaxf(s_redm[l*4+2], s_redm[l*4+3]));
      }
      #pragma unroll
      for (int i = 0; i < 4; i++) {
        int l = lg*4 + i;
        float z = 0.f;
        #pragma unroll
        for (int j = 0; j < 8; j++) {
          float ev = __expf(acc[cc][i][j] - m[i]);
          acc[cc][i][j] = ev;
          z += ev;
        }
        #pragma unroll
        for (int o = 16; o; o >>= 1) z += __shfl_xor_sync(0xffffffffu, z, o);
        if (lane == 0) s_redz[l*4 + w4] = z;
      }
      __syncthreads();
      #pragma unroll
      for (int i = 0; i < 4; i++) {
        int l = lg*4 + i;
        float Z = s_redz[l*4+0] + s_redz[l*4+1] + s_redz[l*4+2] + s_redz[l*4+3];
        float coef = s_pi2[cc*16 + l] / Z;
        #pragma unroll
        for (int j = 0; j < 8; j++)
          s_out[l*SS + si + 128*j] += coef * acc[cc][i][j];
      }
      __syncthreads();   // guard s_redm/s_redz reuse by next code
    }
  }

  // coalesced final write
  float4* og = (float4*)(out + (size_t)((n*HH + h)*LL + l0)*SS);
  const float4* os = (const float4*)s_out;
  for (int idx = tid; idx < TLm*SS/4; idx += 512) og[idx] = os[idx];
}

// ---------------------------------------------------------------------------
extern "C" void kernel_launch(void* const* d_in, const int* in_sizes, int n_in,
                              void* d_out, int out_size)
{
  const float* q    = (const float*)d_in[0];  // [2,1024,8,64]
  const float* key  = (const float*)d_in[1];  // [2,1024,8,64]
  const float* mask = (const float*)d_in[2];  // [2,1024,1024]
  const float* klen = (const float*)d_in[3];  // [2,1024]
  const float* M    = (const float*)d_in[4];  // [8,64,6]
  const float* C    = (const float*)d_in[5];  // [6,8,64,64]
  float* out = (float*)d_out;                 // [2,8,1024,1024]
  (void)in_sizes; (void)n_in; (void)out_size;

  cudaFuncSetAttribute(attn_kernel,
      cudaFuncAttributeMaxDynamicSharedMemorySize, SMEM_BYTES);

  dim3 gpre(LL/64, HH, NB*KK), bpre(256);
  precompute_kernel<<<gpre, bpre>>>(q, M, C);
  dim3 gkey(LL/64, HH, NB), bkey(256);
  keyprep_kernel<<<gkey, bkey>>>(key);
  dim3 gmain(LL/TLm, HH, NB), bmain(512);
  attn_kernel<<<gmain, bmain, SMEM_BYTES>>>(mask, klen, out);
}